// round 1
// baseline (speedup 1.0000x reference)
#include <cuda_runtime.h>
#include <cuda_bf16.h>

#define NN 50000
#define EE 1600000
#define GG 2000
#define CC 64
#define NEG 0.2f

// ---------------- scratch (device globals; no allocation allowed) ----------------
__device__ float  g_xp[NN * 128];        // projected feats [N, H*C] = [N,128]
__device__ float2 g_asrc[NN];            // per-node per-head attn src term
__device__ float2 g_adst[NN];            // per-node per-head attn dst term
__device__ int    g_count[NN];           // in-degree (incl. self loop)
__device__ int    g_rowptr[NN + 1];      // CSR row pointers (by dst)
__device__ int    g_cursor[NN];          // scatter cursors
__device__ int    g_col[EE + NN];        // CSR column (src node per incoming edge)
__device__ int    g_gcnt[GG];            // nodes per graph

// ---------------- 1. projection: xp = x @ W^T  (N x 128 = N x 64 @ 64 x 128) ----
#define NPB 16
__global__ void proj_kernel(const float* __restrict__ x, const float* __restrict__ W) {
    __shared__ float  WsT[64][132];      // WsT[k][j] = W[j][k]; pad row to 132 floats
    __shared__ float4 xs4[NPB][16];      // 16 nodes x 64 floats
    const int t = threadIdx.x;           // 128 threads

    // load W (8192 floats) coalesced from gmem, transpose into smem
    for (int idx = t; idx < 8192; idx += 128) {
        int r = idx >> 6;                // output feature j (0..127)
        int c = idx & 63;                // k (0..63)
        WsT[c][r] = W[idx];
    }
    const int n0 = blockIdx.x * NPB;
    for (int idx = t; idx < NPB * 16; idx += 128) {
        int i = idx >> 4, k4 = idx & 15;
        int n = n0 + i;
        xs4[i][k4] = (n < NN) ? reinterpret_cast<const float4*>(x)[n * 16 + k4]
                              : make_float4(0.f, 0.f, 0.f, 0.f);
    }
    __syncthreads();

    float acc[NPB];
#pragma unroll
    for (int i = 0; i < NPB; i++) acc[i] = 0.f;

#pragma unroll
    for (int k4 = 0; k4 < 16; k4++) {
        float w0 = WsT[4 * k4 + 0][t];
        float w1 = WsT[4 * k4 + 1][t];
        float w2 = WsT[4 * k4 + 2][t];
        float w3 = WsT[4 * k4 + 3][t];
#pragma unroll
        for (int i = 0; i < NPB; i++) {
            float4 xv = xs4[i][k4];
            acc[i] += xv.x * w0 + xv.y * w1 + xv.z * w2 + xv.w * w3;
        }
    }
#pragma unroll
    for (int i = 0; i < NPB; i++) {
        int n = n0 + i;
        if (n < NN) g_xp[n * 128 + t] = acc[i];
    }
}

// ---------------- 2. attention scalars: a_src[n,h], a_dst[n,h] ------------------
__global__ void attn_kernel(const float* __restrict__ att_src,
                            const float* __restrict__ att_dst) {
    int gw   = (blockIdx.x * blockDim.x + threadIdx.x) >> 5;
    int lane = threadIdx.x & 31;
    if (gw >= NN) return;
    float4 v = reinterpret_cast<const float4*>(g_xp)[gw * 32 + lane];
    float4 a = reinterpret_cast<const float4*>(att_src)[lane];
    float4 b = reinterpret_cast<const float4*>(att_dst)[lane];
    float ps = v.x * a.x + v.y * a.y + v.z * a.z + v.w * a.w;
    float pd = v.x * b.x + v.y * b.y + v.z * b.z + v.w * b.w;
#pragma unroll
    for (int o = 8; o; o >>= 1) {
        ps += __shfl_xor_sync(0xffffffffu, ps, o);
        pd += __shfl_xor_sync(0xffffffffu, pd, o);
    }
    float s1 = __shfl_sync(0xffffffffu, ps, 16);
    float d1 = __shfl_sync(0xffffffffu, pd, 16);
    if (lane == 0) {
        g_asrc[gw] = make_float2(ps, s1);
        g_adst[gw] = make_float2(pd, d1);
    }
}

// ---------------- 3. init: degree=1 (self loop), graph counters, graph out ------
__global__ void init_kernel(float* __restrict__ out) {
    int i = blockIdx.x * blockDim.x + threadIdx.x;
    if (i < NN) g_count[i] = 1;
    if (i < GG) g_gcnt[i] = 0;
    if (i < GG * CC) out[NN * CC + i] = 0.f;
}

// ---------------- 4. in-degree histogram over edges -----------------------------
__global__ void hist_kernel(const int* __restrict__ ei) {
    int i = blockIdx.x * blockDim.x + threadIdx.x;
    if (i < EE) atomicAdd(&g_count[ei[EE + i]], 1);
}

// ---------------- 5. nodes-per-graph counts -------------------------------------
__global__ void bcount_kernel(const int* __restrict__ batch) {
    int i = blockIdx.x * blockDim.x + threadIdx.x;
    if (i < NN) atomicAdd(&g_gcnt[batch[i]], 1);
}

// ---------------- 6. exclusive scan of g_count -> g_rowptr (one block) ----------
__global__ void scan_kernel() {
    __shared__ int part[1024];
    const int t  = threadIdx.x;
    const int CH = (NN + 1023) / 1024;
    int base = t * CH;
    int s = 0;
    for (int i = 0; i < CH; i++) {
        int idx = base + i;
        if (idx < NN) s += g_count[idx];
    }
    part[t] = s;
    __syncthreads();
    for (int off = 1; off < 1024; off <<= 1) {
        int v = 0;
        if (t >= off) v = part[t - off];
        __syncthreads();
        if (t >= off) part[t] += v;
        __syncthreads();
    }
    int run = (t == 0) ? 0 : part[t - 1];
    for (int i = 0; i < CH; i++) {
        int idx = base + i;
        if (idx < NN) {
            g_rowptr[idx] = run;
            run += g_count[idx];
        }
    }
    if (t == 1023) g_rowptr[NN] = part[1023];
}

// ---------------- 7. place self loops, init cursors -----------------------------
__global__ void selfloop_kernel() {
    int i = blockIdx.x * blockDim.x + threadIdx.x;
    if (i >= NN) return;
    int p = g_rowptr[i];
    g_col[p] = i;
    g_cursor[i] = p + 1;
}

// ---------------- 8. scatter edges into CSR -------------------------------------
__global__ void scatter_kernel(const int* __restrict__ ei) {
    int i = blockIdx.x * blockDim.x + threadIdx.x;
    if (i >= EE) return;
    int d = ei[EE + i];
    int pos = atomicAdd(&g_cursor[d], 1);
    g_col[pos] = ei[i];
}

// ---------------- 9. softmax-attention aggregation (1 warp / dst node) ----------
__global__ void aggregate_kernel(const float* __restrict__ bias,
                                 float* __restrict__ h_nodes) {
    const int warp = (blockIdx.x * blockDim.x + threadIdx.x) >> 5;
    const int lane = threadIdx.x & 31;
    if (warp >= NN) return;

    const int beg = g_rowptr[warp];
    const int end = g_rowptr[warp + 1];
    const float2 ad = g_adst[warp];

    // pass 1: per-head max of leaky_relu(a_src + a_dst) over incoming edges
    float m0 = -1e30f, m1 = -1e30f;
    for (int j = beg + lane; j < end; j += 32) {
        float2 as = g_asrc[g_col[j]];
        float e0 = as.x + ad.x; e0 = (e0 > 0.f) ? e0 : NEG * e0;
        float e1 = as.y + ad.y; e1 = (e1 > 0.f) ? e1 : NEG * e1;
        m0 = fmaxf(m0, e0);
        m1 = fmaxf(m1, e1);
    }
#pragma unroll
    for (int o = 16; o; o >>= 1) {
        m0 = fmaxf(m0, __shfl_xor_sync(0xffffffffu, m0, o));
        m1 = fmaxf(m1, __shfl_xor_sync(0xffffffffu, m1, o));
    }

    // pass 2: accumulate sum( exp(e-m) * xp[src] ) and sum( exp(e-m) )
    const int h  = lane >> 4;        // head of this lane
    const int ci = lane & 15;        // float4 channel chunk within head
    const float mh = h ? m1 : m0;
    float4 acc = make_float4(0.f, 0.f, 0.f, 0.f);
    float wsum = 0.f;

    for (int base = beg; base < end; base += 32) {
        int j  = base + lane;
        int sj = (j < end) ? g_col[j] : 0;
        float2 as = (j < end) ? g_asrc[sj] : make_float2(-1e30f, -1e30f);
        float e0 = as.x + ad.x; e0 = (e0 > 0.f) ? e0 : NEG * e0;
        float e1 = as.y + ad.y; e1 = (e1 > 0.f) ? e1 : NEG * e1;
        float w0 = __expf(e0 - m0);
        float w1 = __expf(e1 - m1);
        int cnt = end - base; if (cnt > 32) cnt = 32;
        for (int k = 0; k < cnt; k++) {
            int   s  = __shfl_sync(0xffffffffu, sj, k);
            float wa = __shfl_sync(0xffffffffu, w0, k);
            float wb = __shfl_sync(0xffffffffu, w1, k);
            float w  = h ? wb : wa;
            float4 v = reinterpret_cast<const float4*>(g_xp)[s * 32 + h * 16 + ci];
            acc.x += w * v.x;
            acc.y += w * v.y;
            acc.z += w * v.z;
            acc.w += w * v.w;
            wsum  += w;
        }
    }
    float inv = 1.0f / wsum;
    acc.x *= inv; acc.y *= inv; acc.z *= inv; acc.w *= inv;

    // head mean: combine lane l (head0) with lane l+16 (head1), add bias
    float ox = __shfl_xor_sync(0xffffffffu, acc.x, 16);
    float oy = __shfl_xor_sync(0xffffffffu, acc.y, 16);
    float oz = __shfl_xor_sync(0xffffffffu, acc.z, 16);
    float ow = __shfl_xor_sync(0xffffffffu, acc.w, 16);
    if (lane < 16) {
        float4 bv = reinterpret_cast<const float4*>(bias)[ci];
        float4 r;
        r.x = (acc.x + ox) * 0.5f + bv.x;
        r.y = (acc.y + oy) * 0.5f + bv.y;
        r.z = (acc.z + oz) * 0.5f + bv.z;
        r.w = (acc.w + ow) * 0.5f + bv.w;
        reinterpret_cast<float4*>(h_nodes)[warp * 16 + ci] = r;
    }
}

// ---------------- 10. global mean pool ------------------------------------------
__global__ void pool_kernel(const int* __restrict__ batch,
                            const float* __restrict__ h_nodes,
                            float* __restrict__ h_graphs) {
    int tid = blockIdx.x * blockDim.x + threadIdx.x;
    int n  = tid >> 4;
    int ci = tid & 15;
    if (n >= NN) return;
    int g = batch[n];
    int c = g_gcnt[g];
    float inv = 1.0f / (float)(c > 0 ? c : 1);
    float4 v = reinterpret_cast<const float4*>(h_nodes)[n * 16 + ci];
    float* dst = h_graphs + g * CC + ci * 4;
    atomicAdd(dst + 0, v.x * inv);
    atomicAdd(dst + 1, v.y * inv);
    atomicAdd(dst + 2, v.z * inv);
    atomicAdd(dst + 3, v.w * inv);
}

// ---------------- launcher ------------------------------------------------------
extern "C" void kernel_launch(void* const* d_in, const int* in_sizes, int n_in,
                              void* d_out, int out_size) {
    const float* x        = (const float*)d_in[0];
    const int*   ei       = (const int*)  d_in[1];
    const int*   batch    = (const int*)  d_in[2];
    const float* W        = (const float*)d_in[3];
    const float* att_src  = (const float*)d_in[4];
    const float* att_dst  = (const float*)d_in[5];
    const float* bias     = (const float*)d_in[6];
    float* out = (float*)d_out;                    // [N*C | G*C]

    proj_kernel<<<(NN + NPB - 1) / NPB, 128>>>(x, W);
    attn_kernel<<<(NN * 32 + 255) / 256, 256>>>(att_src, att_dst);
    init_kernel<<<(GG * CC + 255) / 256, 256>>>(out);
    hist_kernel<<<(EE + 255) / 256, 256>>>(ei);
    bcount_kernel<<<(NN + 255) / 256, 256>>>(batch);
    scan_kernel<<<1, 1024>>>();
    selfloop_kernel<<<(NN + 255) / 256, 256>>>();
    scatter_kernel<<<(EE + 255) / 256, 256>>>(ei);
    aggregate_kernel<<<(NN * 32 + 255) / 256, 256>>>(bias, out);
    pool_kernel<<<(NN * 16 + 255) / 256, 256>>>(batch, out, out + NN * CC);
}